// round 15
// baseline (speedup 1.0000x reference)
#include <cuda_runtime.h>
#include <math.h>

// Problem constants (B,T,D,U) = (256, 1024, 128, 256)
#define RNN_B 256
#define RNN_T 1024
#define RNN_D 128
#define RNN_U 256

// Scan K-eighth split: per eighth (32 rows), 20 rows of Wh in registers,
// 12 rows streamed from L1 (same addresses all 1024 steps -> resident).
#define KREG 20
#define KLDG 12

#define XT_TILES ((RNN_B * RNN_T) / 64)  // 4096 tiles of 64 rows

typedef unsigned long long u64;

// ---------------------------------------------------------------------------
// Packed fp32x2 helpers (Blackwell FFMA2 path — only reachable via PTX)
// ---------------------------------------------------------------------------
__device__ __forceinline__ u64 ffma2(u64 a, u64 b, u64 c) {
    u64 d;
    asm("fma.rn.f32x2 %0, %1, %2, %3;" : "=l"(d) : "l"(a), "l"(b), "l"(c));
    return d;
}
__device__ __forceinline__ u64 fadd2(u64 a, u64 b) {
    u64 d;
    asm("add.rn.f32x2 %0, %1, %2;" : "=l"(d) : "l"(a), "l"(b));
    return d;
}
__device__ __forceinline__ u64 pack2(float x, float y) {
    u64 r;
    asm("mov.b64 %0, {%1, %2};" : "=l"(r) : "f"(x), "f"(y));
    return r;
}
__device__ __forceinline__ void unpack2(u64 v, float& x, float& y) {
    asm("mov.b64 {%0, %1}, %2;" : "=f"(x), "=f"(y) : "l"(v));
}

// Fast accurate-enough tanh: 1 - 2/(e^{2x}+1). Error ~1e-6.
__device__ __forceinline__ float tanh_fast(float x) {
    float e = __expf(2.0f * x);
    return 1.0f - 2.0f / (e + 1.0f);
}

// ---------------------------------------------------------------------------
// Kernel 1: x_proj = x @ Wx + bias -> d_out. PERSISTENT: 148 CTAs, each
// stages Wx (128 KB) into smem ONCE, then grid-strides over 64-row tiles.
// 512 threads: g = tid>>6 owns 8 rows of the tile, p = tid&63 owns u-quad.
// x tile staged duplicated {v,v}: broadcast LDS.128 = 2 dup-pairs, 1 phase.
// Weights from smem as natural u64 pairs (LDS.128 = both pairs of one d).
// ---------------------------------------------------------------------------
__global__ __launch_bounds__(512, 1) void xproj_kernel(
        const float* __restrict__ x, const float* __restrict__ W,
        const float* __restrict__ bias, float* __restrict__ out) {
    extern __shared__ u64 smem[];
    u64* sW = smem;            // [128 d][128 pair] = 16384 u64 (128 KB)
    u64* sx = smem + 16384;    // [64 r][128 d] dup = 8192 u64 (64 KB)

    const int tid = threadIdx.x;
    const int g = tid >> 6;    // row subgroup 0..7 (8 rows each)
    const int p = tid & 63;    // u-quad index

    // Stage Wx once (u64 pairs, coalesced).
    const u64* wx64 = reinterpret_cast<const u64*>(W + (size_t)RNN_U * RNN_U);
    for (int i = tid; i < 16384; i += 512) sW[i] = wx64[i];

    const ulonglong2 b2 = *reinterpret_cast<const ulonglong2*>(bias + 4 * p);

    for (int tile = blockIdx.x; tile < XT_TILES; tile += gridDim.x) {
        const size_t r0 = (size_t)tile * 64;
        __syncthreads();   // previous tile's sx readers done (also covers sW once)
        for (int idx = tid; idx < 64 * RNN_D; idx += 512) {
            int r = idx >> 7;
            int d = idx & 127;
            float v = x[(r0 + r) * RNN_D + d];
            sx[idx] = pack2(v, v);
        }
        __syncthreads();

        u64 acc0[8], acc1[8];
#pragma unroll
        for (int r = 0; r < 8; r++) { acc0[r] = b2.x; acc1[r] = b2.y; }

        const u64* sxg = sx + (g * 8) * RNN_D;
#pragma unroll 2
        for (int d = 0; d < RNN_D; d += 2) {
            ulonglong2 w0 = *reinterpret_cast<const ulonglong2*>(
                sW + d * 128 + 2 * p);
            ulonglong2 w1 = *reinterpret_cast<const ulonglong2*>(
                sW + (d + 1) * 128 + 2 * p);
#pragma unroll
            for (int r = 0; r < 8; r++) {
                ulonglong2 xv = *reinterpret_cast<const ulonglong2*>(
                    sxg + r * RNN_D + d);   // {x[r][d]dup, x[r][d+1]dup}
                acc0[r] = ffma2(w0.x, xv.x, acc0[r]);
                acc1[r] = ffma2(w0.y, xv.x, acc1[r]);
                acc0[r] = ffma2(w1.x, xv.y, acc0[r]);
                acc1[r] = ffma2(w1.y, xv.y, acc1[r]);
            }
        }
#pragma unroll
        for (int r = 0; r < 8; r++)
            *reinterpret_cast<ulonglong2*>(
                out + (r0 + g * 8 + r) * RNN_U + 4 * p) =
                make_ulonglong2(acc0[r], acc1[r]);
    }
}

// ---------------------------------------------------------------------------
// Kernel 2: persistent scan. 128 CTAs x 512 threads (4 warps/SMSP), 2 batches.
//   s = tid>>6 : K-eighth (k in [32s, 32s+32))
//   p = tid&63 : u-quad (pairs 2p, 2p+1)
// Wh: 20 rows/thread in registers (80 regs -> <=128 total, 4 warps/SMSP for
// latency hiding), 12 rows via L1-resident global loads. h duplicated {h,h};
// broadcast LDS.128 = 2 dup-pairs per crossbar phase.
// Step: MAC -> publish partials (parity-buffered) -> full barrier ->
// 256 threads finalize one output pair each (8-way tree + xp + tanh +
// writeback + h refresh) -> full barrier.
// ---------------------------------------------------------------------------
__global__ __launch_bounds__(512, 1) void rnn_scan_kernel(
        const float* __restrict__ W, const float* __restrict__ h0,
        float* __restrict__ out) {
    __shared__ u64 sh[2 * RNN_U];           // [batch][u] dup h (4 KB)
    __shared__ u64 sred[2 * 2 * 8 * 128];   // [parity][batch][group][pair] (32 KB)

    const int tid = threadIdx.x;
    const int s = tid >> 6;                 // K-eighth
    const int p = tid & 63;                 // u-quad
    const int b0 = blockIdx.x * 2;

    // Register-resident Wh: k = 32s + j, j in [0,KREG).
    u64 wr0[KREG], wr1[KREG];
    {
        const float* wb = W + (size_t)(32 * s) * RNN_U + 4 * p;
#pragma unroll
        for (int j = 0; j < KREG; j++) {
            ulonglong2 w = *reinterpret_cast<const ulonglong2*>(
                wb + (size_t)j * RNN_U);
            wr0[j] = w.x;
            wr1[j] = w.y;
        }
    }
    const float* wtail = W + (size_t)(32 * s + KREG) * RNN_U + 4 * p;

    // Initial h (duplicated lanes): exactly one element per thread.
    {
        int b = tid >> 8;
        int u = tid & 255;
        float h = h0[(size_t)(b0 + b) * RNN_U + u];
        sh[tid] = pack2(h, h);
    }
    __syncthreads();

    const u64* sh0 = sh + 32 * s;           // batch 0 h slice, this eighth
    const u64* sh1 = sh + RNN_U + 32 * s;   // batch 1

    // Finalize task (tid < 256): batch fb, output pair fpp.
    const bool isfin = tid < 256;
    const int fb  = (tid >> 7) & 1;
    const int fpp = tid & 127;
    float* fout = out + (size_t)(b0 + fb) * RNN_T * RNN_U + 2 * fpp;
    u64* fsh = sh + fb * RNN_U + 2 * fpp;

    for (int t = 0; t < RNN_T; t++) {
        const int buf = t & 1;

        // Prefetch this step's x_proj (consumed after the barrier).
        u64 xp = 0;
        if (isfin) xp = *reinterpret_cast<const u64*>(fout + (size_t)t * RNN_U);

        u64 a00 = 0, a01 = 0, a10 = 0, a11 = 0;

        // Streamed-weight MACs first (loads issue early; L1-resident).
#pragma unroll
        for (int j = 0; j < KLDG; j += 2) {
            ulonglong2 w0 = *reinterpret_cast<const ulonglong2*>(
                wtail + (size_t)j * RNN_U);
            ulonglong2 w1 = *reinterpret_cast<const ulonglong2*>(
                wtail + (size_t)(j + 1) * RNN_U);
            ulonglong2 hb0 = *reinterpret_cast<const ulonglong2*>(sh0 + KREG + j);
            ulonglong2 hb1 = *reinterpret_cast<const ulonglong2*>(sh1 + KREG + j);
            a00 = ffma2(w0.x, hb0.x, a00);
            a01 = ffma2(w0.y, hb0.x, a01);
            a10 = ffma2(w0.x, hb1.x, a10);
            a11 = ffma2(w0.y, hb1.x, a11);
            a00 = ffma2(w1.x, hb0.y, a00);
            a01 = ffma2(w1.y, hb0.y, a01);
            a10 = ffma2(w1.x, hb1.y, a10);
            a11 = ffma2(w1.y, hb1.y, a11);
        }
        // Register-weight MACs: 20 rows, 2 batches, 2 pairs.
#pragma unroll
        for (int j = 0; j < KREG; j += 2) {
            ulonglong2 hb0 = *reinterpret_cast<const ulonglong2*>(sh0 + j);
            ulonglong2 hb1 = *reinterpret_cast<const ulonglong2*>(sh1 + j);
            a00 = ffma2(wr0[j],     hb0.x, a00);
            a01 = ffma2(wr1[j],     hb0.x, a01);
            a10 = ffma2(wr0[j],     hb1.x, a10);
            a11 = ffma2(wr1[j],     hb1.x, a11);
            a00 = ffma2(wr0[j + 1], hb0.y, a00);
            a01 = ffma2(wr1[j + 1], hb0.y, a01);
            a10 = ffma2(wr0[j + 1], hb1.y, a10);
            a11 = ffma2(wr1[j + 1], hb1.y, a11);
        }

        // Publish partials (parity-buffered against cross-step WAR).
        *reinterpret_cast<ulonglong2*>(
            &sred[((buf * 2 + 0) * 8 + s) * 128 + 2 * p]) =
            make_ulonglong2(a00, a01);
        *reinterpret_cast<ulonglong2*>(
            &sred[((buf * 2 + 1) * 8 + s) * 128 + 2 * p]) =
            make_ulonglong2(a10, a11);
        __syncthreads();   // partials visible; all sh reads complete

        if (isfin) {
            const u64* rb = &sred[(buf * 2 + fb) * 8 * 128 + fpp];
            u64 z0 = fadd2(rb[0 * 128], rb[1 * 128]);
            u64 z1 = fadd2(rb[2 * 128], rb[3 * 128]);
            u64 z2 = fadd2(rb[4 * 128], rb[5 * 128]);
            u64 z3 = fadd2(rb[6 * 128], rb[7 * 128]);
            u64 z = fadd2(fadd2(z0, z1), fadd2(z2, z3));
            z = fadd2(z, xp);
            float f0, f1;
            unpack2(z, f0, f1);
            f0 = tanh_fast(f0);
            f1 = tanh_fast(f1);
            // Output (overwrites x_proj slot for this t, in place).
            *reinterpret_cast<u64*>(fout + (size_t)t * RNN_U) = pack2(f0, f1);
            // Refresh duplicated h for next step.
            *reinterpret_cast<ulonglong2*>(fsh) =
                make_ulonglong2(pack2(f0, f0), pack2(f1, f1));
        }
        __syncthreads();   // new h visible before next step's reads
    }
}

// ---------------------------------------------------------------------------
// Launch: x_proj fills d_out, then the scan rewrites it in place.
// Inputs (metadata order): x, h0, W, bias. Output dtype float32.
// ---------------------------------------------------------------------------
extern "C" void kernel_launch(void* const* d_in, const int* in_sizes, int n_in,
                              void* d_out, int out_size) {
    const float* x    = (const float*)d_in[0];
    const float* h0   = (const float*)d_in[1];
    const float* W    = (const float*)d_in[2];
    const float* bias = (const float*)d_in[3];
    float* out = (float*)d_out;

    const int xproj_smem = (16384 + 8192) * 8;   // 196608 B
    cudaFuncSetAttribute(xproj_kernel,
                         cudaFuncAttributeMaxDynamicSharedMemorySize, xproj_smem);

    xproj_kernel<<<148, 512, xproj_smem>>>(x, W, bias, out);
    rnn_scan_kernel<<<RNN_B / 2, 512>>>(W, h0, out);
}